// round 12
// baseline (speedup 1.0000x reference)
#include <cuda_runtime.h>
#include <cuda_bf16.h>
#include <math.h>
#include <stdint.h>

// Problem constants
#define T_STEPS 512
#define BATCH   128
#define DIN     256
#define HID     256
#define NCOLS   2048            // dir*1024 + gate*256 + j
#define OUT_TB_STRIDE 512
#define OUT_MAIN (T_STEPS*BATCH*OUT_TB_STRIDE)

#define CTAS_PER_DIR 16
#define GEMM_BLKS_PER_T 16

// xg scratch, layout [t][ncol(2048)][b(128)] fp32 (536 MB)
__device__ float g_xg[(size_t)T_STEPS * NCOLS * BATCH];
// h ping-pong, packed bf16 hi|lo<<16 per element: [dir][buf][b(128)][k(256)]
__device__ uint32_t g_hpk[2][2][BATCH][HID];
// sync counters
__device__ int g_bar[2][T_STEPS];
__device__ int g_xg_ready[T_STEPS];

__device__ __forceinline__ float sigm(float x) { return 1.f / (1.f + expf(-x)); }

__device__ __forceinline__ uint32_t pack_hilo(float v) {
    __nv_bfloat16 hh = __float2bfloat16(v);
    __nv_bfloat16 hl = __float2bfloat16(v - __bfloat162float(hh));
    uint16_t uh = *reinterpret_cast<uint16_t*>(&hh);
    uint16_t ul = *reinterpret_cast<uint16_t*>(&hl);
    return (uint32_t)uh | ((uint32_t)ul << 16);
}

// mma.sync m16n8k16 row.col f32.bf16.bf16.f32  (baseline PTX, sm_80+)
__device__ __forceinline__ void mma_bf16(float* d, const uint32_t* a, const uint32_t* b) {
    asm volatile(
        "mma.sync.aligned.m16n8k16.row.col.f32.bf16.bf16.f32 "
        "{%0,%1,%2,%3}, {%4,%5,%6,%7}, {%8,%9}, {%0,%1,%2,%3};"
        : "+f"(d[0]), "+f"(d[1]), "+f"(d[2]), "+f"(d[3])
        : "r"(a[0]), "r"(a[1]), "r"(a[2]), "r"(a[3]), "r"(b[0]), "r"(b[1]));
}

// ---------------------------------------------------------------------------
// Phase 1: xg = X @ Wcat^T + (b_ih + b_hh), written as [t][ncol][b].
// bm interleaved from both ends so both recurrence directions are fed early.
// ---------------------------------------------------------------------------
__global__ __launch_bounds__(256) void gemm_xg_kernel(
    const float* __restrict__ X,
    const float* __restrict__ Wf, const float* __restrict__ Wb,
    const float* __restrict__ bif, const float* __restrict__ bhf,
    const float* __restrict__ bib, const float* __restrict__ bhb)
{
    const int bn = blockIdx.x;     // 0..15
    const int bm = blockIdx.y;     // 0..511
    const int t  = (bm & 1) ? (T_STEPS - 1 - (bm >> 1)) : (bm >> 1);
    const bool fwd = (bn < 8);
    const float* W  = fwd ? (Wf + (size_t)bn * 128 * DIN)
                          : (Wb + (size_t)(bn - 8) * 128 * DIN);
    const float* bi = fwd ? bif : bib;
    const float* bh = fwd ? bhf : bhb;
    const int nloc_base = (fwd ? bn : bn - 8) * 128;

    __shared__ float As[16][132];
    __shared__ float Bs[16][132];

    const int tid = threadIdx.x;
    const int tx = tid & 15, ty = tid >> 4;

    float acc[8][8];
    #pragma unroll
    for (int i = 0; i < 8; i++)
        #pragma unroll
        for (int j = 0; j < 8; j++) acc[i][j] = 0.f;

    const int loadRow = tid >> 2;
    const int loadK4  = (tid & 3) * 4;
    const float* Abase = X + (size_t)t * 128 * DIN;

    for (int k0 = 0; k0 < DIN; k0 += 16) {
        #pragma unroll
        for (int r = 0; r < 2; r++) {
            int row = loadRow + r * 64;
            float4 va = *(const float4*)(Abase + (size_t)row * DIN + k0 + loadK4);
            As[loadK4 + 0][row] = va.x; As[loadK4 + 1][row] = va.y;
            As[loadK4 + 2][row] = va.z; As[loadK4 + 3][row] = va.w;
            float4 vb = *(const float4*)(W + (size_t)row * DIN + k0 + loadK4);
            Bs[loadK4 + 0][row] = vb.x; Bs[loadK4 + 1][row] = vb.y;
            Bs[loadK4 + 2][row] = vb.z; Bs[loadK4 + 3][row] = vb.w;
        }
        __syncthreads();
        #pragma unroll
        for (int k = 0; k < 16; k++) {
            float a[8], b[8];
            float4 a0 = *(const float4*)&As[k][ty * 8];
            float4 a1 = *(const float4*)&As[k][ty * 8 + 4];
            float4 b0 = *(const float4*)&Bs[k][tx * 8];
            float4 b1 = *(const float4*)&Bs[k][tx * 8 + 4];
            a[0]=a0.x; a[1]=a0.y; a[2]=a0.z; a[3]=a0.w;
            a[4]=a1.x; a[5]=a1.y; a[6]=a1.z; a[7]=a1.w;
            b[0]=b0.x; b[1]=b0.y; b[2]=b0.z; b[3]=b0.w;
            b[4]=b1.x; b[5]=b1.y; b[6]=b1.z; b[7]=b1.w;
            #pragma unroll
            for (int i = 0; i < 8; i++)
                #pragma unroll
                for (int j = 0; j < 8; j++)
                    acc[i][j] += a[i] * b[j];
        }
        __syncthreads();
    }

    #pragma unroll
    for (int j = 0; j < 8; j++) {
        int nloc = tx * 8 + j;
        float bv = bi[nloc_base + nloc] + bh[nloc_base + nloc];
        int ncol = bn * 128 + nloc;
        float* base = g_xg + ((size_t)t * NCOLS + ncol) * BATCH + ty * 8;
        *(float4*)(base)     = make_float4(acc[0][j]+bv, acc[1][j]+bv, acc[2][j]+bv, acc[3][j]+bv);
        *(float4*)(base + 4) = make_float4(acc[4][j]+bv, acc[5][j]+bv, acc[6][j]+bv, acc[7][j]+bv);
    }

    __threadfence();
    __syncthreads();
    if (tid == 0) atomicAdd(&g_xg_ready[t], 1);
}

// ---------------------------------------------------------------------------
// init: zero counters; h0 -> g_hpk buf 1 (step 0 reads buf (0+1)&1 = 1)
// ---------------------------------------------------------------------------
__global__ void init_misc_kernel(const float* __restrict__ h0)
{
    int i = blockIdx.x * 256 + threadIdx.x;   // 0..65535 (grid 256)
    ((uint32_t*)g_hpk)[(size_t)(i >> 15) * 2 * 32768 + 32768 + (i & 32767)] =
        pack_hilo(h0[i]);
    if (i < 2 * T_STEPS) ((int*)g_bar)[i] = 0;
    if (i < T_STEPS) g_xg_ready[i] = 0;
}

// ---------------------------------------------------------------------------
// Persistent HMMA recurrence.
// grid = 32 CTAs: dir = blk>>4, q = blk&15 owns j in [q*16, q*16+16).
// 128 threads = 4 warps; warp w owns batches [w*32, w*32+32) (mt 0/1).
// Per-CTA GEMM: M=128 (batch), N=64 (4 gates x 16 j, n = gate*16+jj),
// K=256, bf16x3 (Ah*Bh + Al*Bh + Ah*Bl), fp32 accum, D init = xg (prefetched
// before the h barrier).
// ---------------------------------------------------------------------------
#define HS_STRIDE 264                       // bf16 elements per padded row
#define HS_ELEMS  (128 * HS_STRIDE)
#define WS_ELEMS  (64 * HS_STRIDE)
#define SMEM_TOTAL ((2 * HS_ELEMS + 2 * WS_ELEMS) * 2)   // 202,752 B

extern "C" __global__ void __launch_bounds__(128) lstm_mma_kernel(
    const float* __restrict__ Whh_f, const float* __restrict__ Whh_b,
    const float* __restrict__ c0, float* __restrict__ out)
{
    extern __shared__ __nv_bfloat16 smem[];
    __nv_bfloat16* hs_hi = smem;
    __nv_bfloat16* hs_lo = smem + HS_ELEMS;
    __nv_bfloat16* ws_hi = smem + 2 * HS_ELEMS;
    __nv_bfloat16* ws_lo = smem + 2 * HS_ELEMS + WS_ELEMS;

    const int blk = blockIdx.x;
    const int dir = blk >> 4;
    const int q   = blk & 15;
    const int tid = threadIdx.x;
    const int w   = tid >> 5;
    const int ln  = tid & 31;
    const int grp = ln >> 2;                // 0..7
    const int tig = ln & 3;                 // 0..3

    const float* Whh = dir ? Whh_b : Whh_f;

    // ---- W_hh slice: 64 rows, n = gate*16 + jj -> wrow = gate*256 + q*16 + jj
    for (int i = tid; i < 64 * HID; i += 128) {
        int n = i >> 8, k = i & 255;
        int wrow = (n >> 4) * HID + q * 16 + (n & 15);
        float wv = Whh[(size_t)wrow * HID + k];
        __nv_bfloat16 wh = __float2bfloat16(wv);
        ws_hi[n * HS_STRIDE + k] = wh;
        ws_lo[n * HS_STRIDE + k] = __float2bfloat16(wv - __bfloat162float(wh));
    }

    // ---- cell state: 16 cells = (2 mt)(2 ntp)(2 rr)(2 jb) ----
    float cr[16];
    #pragma unroll
    for (int mt = 0; mt < 2; mt++)
        #pragma unroll
        for (int ntp = 0; ntp < 2; ntp++)
            #pragma unroll
            for (int rr = 0; rr < 2; rr++)
                #pragma unroll
                for (int jb = 0; jb < 2; jb++) {
                    int b = w * 32 + mt * 16 + grp + rr * 8;
                    int j = q * 16 + ntp * 8 + tig * 2 + jb;
                    cr[mt * 8 + ntp * 4 + rr * 2 + jb] =
                        c0[(size_t)dir * BATCH * HID + (size_t)b * HID + j];
                }

    __syncthreads();

    for (int s = 0; s < T_STEPS; s++) {
        const int t = dir ? (T_STEPS - 1 - s) : s;

        // ---- wait: xg[t] produced ----
        if (tid == 0) {
            volatile int* px = &g_xg_ready[t];
            while (*px < GEMM_BLKS_PER_T) __nanosleep(64);
        }
        __syncthreads();

        // ---- prefetch xg into accumulators (overlaps the h barrier wait) ----
        float acc[2][8][4];
        #pragma unroll
        for (int mt = 0; mt < 2; mt++)
            #pragma unroll
            for (int nt = 0; nt < 8; nt++)
                #pragma unroll
                for (int rr = 0; rr < 2; rr++)
                    #pragma unroll
                    for (int jb = 0; jb < 2; jb++) {
                        int b = w * 32 + mt * 16 + grp + rr * 8;
                        int ncol = dir * 1024 + (nt >> 1) * 256
                                 + q * 16 + (nt & 1) * 8 + tig * 2 + jb;
                        acc[mt][nt][rr * 2 + jb] =
                            __ldcg(g_xg + ((size_t)t * NCOLS + ncol) * BATCH + b);
                    }

        // ---- wait: all CTAs of this dir finished step s-1 ----
        if (s > 0) {
            if (tid == 0) {
                volatile int* p = &g_bar[dir][s - 1];
                while (*p < CTAS_PER_DIR) __nanosleep(32);
            }
        }
        __syncthreads();

        // ---- stage packed h [128 x 256] -> hi/lo SMEM planes ----
        {
            const uint4* src = (const uint4*)&g_hpk[dir][(s + 1) & 1][0][0];
            #pragma unroll 4
            for (int i = tid; i < 8192; i += 128) {     // uint4 = 4 packed elems
                int b = i >> 6, kq = i & 63;            // k = kq*4
                uint4 v = __ldcv(src + i);
                uint32_t u0 = (v.x & 0xFFFFu) | (v.y << 16);
                uint32_t u1 = (v.z & 0xFFFFu) | (v.w << 16);
                uint32_t l0 = (v.x >> 16) | (v.y & 0xFFFF0000u);
                uint32_t l1 = (v.z >> 16) | (v.w & 0xFFFF0000u);
                *(uint2*)&hs_hi[b * HS_STRIDE + kq * 4] = make_uint2(u0, u1);
                *(uint2*)&hs_lo[b * HS_STRIDE + kq * 4] = make_uint2(l0, l1);
            }
        }
        __syncthreads();

        // ---- K loop: 16 k-tiles x (2 mt x 8 nt) x 3 passes ----
        #pragma unroll 2
        for (int kt = 0; kt < 16; kt++) {
            const int k0 = kt * 16 + tig * 2;
            uint32_t Ah[2][4], Al[2][4], Bh[8][2], Bl[8][2];
            #pragma unroll
            for (int mt = 0; mt < 2; mt++) {
                int b = w * 32 + mt * 16 + grp;
                Ah[mt][0] = *(const uint32_t*)&hs_hi[(b    ) * HS_STRIDE + k0];
                Ah[mt][1] = *(const uint32_t*)&hs_hi[(b + 8) * HS_STRIDE + k0];
                Ah[mt][2] = *(const uint32_t*)&hs_hi[(b    ) * HS_STRIDE + k0 + 8];
                Ah[mt][3] = *(const uint32_t*)&hs_hi[(b + 8) * HS_STRIDE + k0 + 8];
                Al[mt][0] = *(const uint32_t*)&hs_lo[(b    ) * HS_STRIDE + k0];
                Al[mt][1] = *(const uint32_t*)&hs_lo[(b + 8) * HS_STRIDE + k0];
                Al[mt][2] = *(const uint32_t*)&hs_lo[(b    ) * HS_STRIDE + k0 + 8];
                Al[mt][3] = *(const uint32_t*)&hs_lo[(b + 8) * HS_STRIDE + k0 + 8];
            }
            #pragma unroll
            for (int nt = 0; nt < 8; nt++) {
                int n = nt * 8 + grp;
                Bh[nt][0] = *(const uint32_t*)&ws_hi[n * HS_STRIDE + k0];
                Bh[nt][1] = *(const uint32_t*)&ws_hi[n * HS_STRIDE + k0 + 8];
                Bl[nt][0] = *(const uint32_t*)&ws_lo[n * HS_STRIDE + k0];
                Bl[nt][1] = *(const uint32_t*)&ws_lo[n * HS_STRIDE + k0 + 8];
            }
            #pragma unroll
            for (int mt = 0; mt < 2; mt++)
                #pragma unroll
                for (int nt = 0; nt < 8; nt++) {
                    mma_bf16(acc[mt][nt], Ah[mt], Bh[nt]);
                    mma_bf16(acc[mt][nt], Al[mt], Bh[nt]);
                    mma_bf16(acc[mt][nt], Ah[mt], Bl[nt]);
                }
        }

        // ---- epilogue: gates, c/h update, publish ----
        uint32_t* hdst = &g_hpk[dir][s & 1][0][0];
        #pragma unroll
        for (int mt = 0; mt < 2; mt++)
            #pragma unroll
            for (int ntp = 0; ntp < 2; ntp++)
                #pragma unroll
                for (int rr = 0; rr < 2; rr++) {
                    int b = w * 32 + mt * 16 + grp + rr * 8;
                    int j = q * 16 + ntp * 8 + tig * 2;     // jb=0; jb=1 is j+1
                    float hn2[2], cn2[2];
                    #pragma unroll
                    for (int jb = 0; jb < 2; jb++) {
                        int di = rr * 2 + jb;
                        int ci = mt * 8 + ntp * 4 + rr * 2 + jb;
                        float Gi = acc[mt][0 * 2 + ntp][di];
                        float Gf = acc[mt][1 * 2 + ntp][di];
                        float Gg = acc[mt][2 * 2 + ntp][di];
                        float Go = acc[mt][3 * 2 + ntp][di];
                        float cn = sigm(Gf) * cr[ci] + sigm(Gi) * tanhf(Gg);
                        float hn = sigm(Go) * tanhf(cn);
                        cr[ci] = cn; hn2[jb] = hn; cn2[jb] = cn;
                    }
                    *(float2*)(out + (size_t)t * BATCH * OUT_TB_STRIDE
                               + (size_t)b * OUT_TB_STRIDE + dir * HID + j)
                        = make_float2(hn2[0], hn2[1]);
                    *(uint2*)(hdst + (size_t)b * HID + j)
                        = make_uint2(pack_hilo(hn2[0]), pack_hilo(hn2[1]));
                    if (s == T_STEPS - 1) {
                        float* tail_h = out + OUT_MAIN + dir * 65536;
                        float* tail_c = tail_h + 32768;
                        *(float2*)(tail_h + b * HID + j) = make_float2(hn2[0], hn2[1]);
                        *(float2*)(tail_c + b * HID + j) = make_float2(cn2[0], cn2[1]);
                    }
                }

        // ---- release ----
        __threadfence();
        __syncthreads();
        if (tid == 0) atomicAdd(&g_bar[dir][s], 1);
    }
}

// ---------------------------------------------------------------------------
extern "C" void kernel_launch(void* const* d_in, const int* in_sizes, int n_in,
                              void* d_out, int out_size)
{
    const float* x     = (const float*)d_in[0];
    const float* h0    = (const float*)d_in[1];
    const float* c0    = (const float*)d_in[2];
    const float* Wih_f = (const float*)d_in[3];
    const float* Whh_f = (const float*)d_in[4];
    const float* bih_f = (const float*)d_in[5];
    const float* bhh_f = (const float*)d_in[6];
    const float* Wih_b = (const float*)d_in[7];
    const float* Whh_b = (const float*)d_in[8];
    const float* bih_b = (const float*)d_in[9];
    const float* bhh_b = (const float*)d_in[10];
    float* out = (float*)d_out;

    static cudaStream_t s_gemm = nullptr;
    static cudaEvent_t ev_fork = nullptr, ev_join = nullptr;
    if (!s_gemm) {
        cudaStreamCreateWithFlags(&s_gemm, cudaStreamNonBlocking);
        cudaEventCreateWithFlags(&ev_fork, cudaEventDisableTiming);
        cudaEventCreateWithFlags(&ev_join, cudaEventDisableTiming);
    }

    cudaFuncSetAttribute(lstm_mma_kernel,
                         cudaFuncAttributeMaxDynamicSharedMemorySize, SMEM_TOTAL);

    init_misc_kernel<<<256, 256>>>(h0);

    // fork: xg gemm runs concurrently, feeding the recurrence per-t
    cudaEventRecord(ev_fork, 0);
    cudaStreamWaitEvent(s_gemm, ev_fork, 0);
    gemm_xg_kernel<<<dim3(16, 512), 256, 0, s_gemm>>>(
        x, Wih_f, Wih_b, bih_f, bhh_f, bih_b, bhh_b);
    cudaEventRecord(ev_join, s_gemm);

    // main stream: persistent HMMA recurrence
    lstm_mma_kernel<<<2 * CTAS_PER_DIR, 128, SMEM_TOTAL>>>(Whh_f, Whh_b, c0, out);

    cudaStreamWaitEvent(0, ev_join, 0);
}

// round 16
// speedup vs baseline: 1.7523x; 1.7523x over previous
#include <cuda_runtime.h>
#include <cuda_bf16.h>
#include <math.h>
#include <stdint.h>

// Problem constants
#define T_STEPS 512
#define BATCH   128
#define DIN     256
#define HID     256
#define NCOLS   2048            // dir*1024 + gate*256 + j
#define OUT_TB_STRIDE 512
#define OUT_MAIN (T_STEPS*BATCH*OUT_TB_STRIDE)

#define CTAS_PER_DIR 32
#define GEMM_BLKS_PER_T 16      // 16 mtiles of 128 ncols each

// xg scratch, layout [t][ncol(2048)][b(128)] fp32 (536 MB)
__device__ float g_xg[(size_t)T_STEPS * NCOLS * BATCH];
// bf16 hi/lo planes of X ([t*128+b][k]) and Wcat ([ncol][k])
__device__ __nv_bfloat16 g_xhi[(size_t)T_STEPS * BATCH * DIN];
__device__ __nv_bfloat16 g_xlo[(size_t)T_STEPS * BATCH * DIN];
__device__ __nv_bfloat16 g_whi[NCOLS * DIN];
__device__ __nv_bfloat16 g_wlo[NCOLS * DIN];
__device__ float g_bias[NCOLS];
// h ping-pong, bf16 hi/lo planes: [dir][buf][hilo][b(128)][k(256)]
__device__ __nv_bfloat16 g_hbf[2][2][2][BATCH][HID];
// sync counters
__device__ int g_bar[2][T_STEPS];
__device__ int g_xg_ready[T_STEPS];

__device__ __forceinline__ float sigm(float x) { return 1.f / (1.f + expf(-x)); }

// mma.sync m16n8k16 row.col f32.bf16.bf16.f32  (baseline PTX, sm_80+)
__device__ __forceinline__ void mma_bf16(float* d, const uint32_t* a, const uint32_t* b) {
    asm volatile(
        "mma.sync.aligned.m16n8k16.row.col.f32.bf16.bf16.f32 "
        "{%0,%1,%2,%3}, {%4,%5,%6,%7}, {%8,%9}, {%0,%1,%2,%3};"
        : "+f"(d[0]), "+f"(d[1]), "+f"(d[2]), "+f"(d[3])
        : "r"(a[0]), "r"(a[1]), "r"(a[2]), "r"(a[3]), "r"(b[0]), "r"(b[1]));
}

// ---------------------------------------------------------------------------
// init kernels: hi/lo splits + counters + h0 conversion
// ---------------------------------------------------------------------------
__global__ void split_w_kernel(
    const float* __restrict__ Wf, const float* __restrict__ Wb,
    const float* __restrict__ bif, const float* __restrict__ bhf,
    const float* __restrict__ bib, const float* __restrict__ bhb)
{
    int idx = blockIdx.x * 256 + threadIdx.x;     // 0..524287
    int row = idx >> 8, k = idx & 255;
    int dir = row >> 10, r = row & 1023;
    float v = (dir ? Wb : Wf)[r * DIN + k];
    __nv_bfloat16 hi = __float2bfloat16(v);
    g_whi[idx] = hi;
    g_wlo[idx] = __float2bfloat16(v - __bfloat162float(hi));
    if (idx < NCOLS) {
        int d2 = idx >> 10, r2 = idx & 1023;
        g_bias[idx] = (d2 ? bib[r2] : bif[r2]) + (d2 ? bhb[r2] : bhf[r2]);
    }
}

__global__ void split_x_kernel(const float* __restrict__ X)
{
    size_t i = ((size_t)blockIdx.x * 256 + threadIdx.x) * 8;   // 8192 blocks
    float4 a = *(const float4*)(X + i);
    float4 b = *(const float4*)(X + i + 4);
    __nv_bfloat16 hi[8], lo[8];
    float v[8] = {a.x,a.y,a.z,a.w,b.x,b.y,b.z,b.w};
    #pragma unroll
    for (int c = 0; c < 8; c++) {
        hi[c] = __float2bfloat16(v[c]);
        lo[c] = __float2bfloat16(v[c] - __bfloat162float(hi[c]));
    }
    *(uint4*)(g_xhi + i) = *(uint4*)hi;
    *(uint4*)(g_xlo + i) = *(uint4*)lo;
}

__global__ void init_misc_kernel(const float* __restrict__ h0)
{
    int i = blockIdx.x * 256 + threadIdx.x;   // 0..65535 (grid 256)
    int dir = i >> 15;
    int rem = i & 32767;                       // b*HID + k
    float h = h0[i];
    __nv_bfloat16 hh = __float2bfloat16(h);
    __nv_bfloat16 hl = __float2bfloat16(h - __bfloat162float(hh));
    ((__nv_bfloat16*)g_hbf)[((size_t)(dir * 2 + 1) * 2 + 0) * 32768 + rem] = hh;
    ((__nv_bfloat16*)g_hbf)[((size_t)(dir * 2 + 1) * 2 + 1) * 32768 + rem] = hl;
    if (i < 2 * T_STEPS) ((int*)g_bar)[i] = 0;
    if (i < T_STEPS) g_xg_ready[i] = 0;
}

// ---------------------------------------------------------------------------
// Phase 1 HMMA gemm: xg[t][ncol][b] = Wcat @ X[t]^T + bias  (bf16x3).
// grid (16 mtile, 512 bm->t both-ends), 512 threads = 16 warps (4m x 4n).
// CTA tile: M=128 ncols x N=128 batch x K=256 (4 chunks of 64).
// A = W planes (row m = ncol), B = X planes (row n = batch) -> fragment rows
// are ncol, cols are batch: stores land contiguous in [ncol][b] layout.
// ---------------------------------------------------------------------------
#define GS_STRIDE 72
#define GEMM_SMEM (4 * 128 * GS_STRIDE * 2)     // 73,728 B

__global__ __launch_bounds__(512) void gemm_hmma_kernel()
{
    extern __shared__ __nv_bfloat16 gsm[];
    __nv_bfloat16* As_hi = gsm;
    __nv_bfloat16* As_lo = gsm + 128 * GS_STRIDE;
    __nv_bfloat16* Bs_hi = gsm + 2 * 128 * GS_STRIDE;
    __nv_bfloat16* Bs_lo = gsm + 3 * 128 * GS_STRIDE;

    const int mtile = blockIdx.x;           // 0..15
    const int bm    = blockIdx.y;           // 0..511
    const int t     = (bm & 1) ? (T_STEPS - 1 - (bm >> 1)) : (bm >> 1);
    const int tid   = threadIdx.x;
    const int warp  = tid >> 5;
    const int wm    = warp >> 2;            // 0..3
    const int wn    = warp & 3;             // 0..3
    const int ln    = tid & 31;
    const int grp   = ln >> 2;
    const int tig   = ln & 3;

    const int ldRow = tid >> 2;             // 0..127
    const int ldSeg = tid & 3;              // 0..3 (16 bf16 each)

    float acc[2][4][4];
    #pragma unroll
    for (int mt = 0; mt < 2; mt++)
        #pragma unroll
        for (int nt = 0; nt < 4; nt++)
            #pragma unroll
            for (int c = 0; c < 4; c++) acc[mt][nt][c] = 0.f;

    const size_t wbase = (size_t)(mtile * 128) * DIN;
    const size_t xbase = (size_t)t * BATCH * DIN;

    for (int kc = 0; kc < 4; kc++) {
        const int koff = kc * 64 + ldSeg * 16;
        {
            uint4 a0 = *(const uint4*)(g_whi + wbase + (size_t)ldRow * DIN + koff);
            uint4 a1 = *(const uint4*)(g_whi + wbase + (size_t)ldRow * DIN + koff + 8);
            uint4 a2 = *(const uint4*)(g_wlo + wbase + (size_t)ldRow * DIN + koff);
            uint4 a3 = *(const uint4*)(g_wlo + wbase + (size_t)ldRow * DIN + koff + 8);
            uint4 b0 = *(const uint4*)(g_xhi + xbase + (size_t)ldRow * DIN + koff);
            uint4 b1 = *(const uint4*)(g_xhi + xbase + (size_t)ldRow * DIN + koff + 8);
            uint4 b2 = *(const uint4*)(g_xlo + xbase + (size_t)ldRow * DIN + koff);
            uint4 b3 = *(const uint4*)(g_xlo + xbase + (size_t)ldRow * DIN + koff + 8);
            *(uint4*)&As_hi[ldRow * GS_STRIDE + ldSeg * 16]     = a0;
            *(uint4*)&As_hi[ldRow * GS_STRIDE + ldSeg * 16 + 8] = a1;
            *(uint4*)&As_lo[ldRow * GS_STRIDE + ldSeg * 16]     = a2;
            *(uint4*)&As_lo[ldRow * GS_STRIDE + ldSeg * 16 + 8] = a3;
            *(uint4*)&Bs_hi[ldRow * GS_STRIDE + ldSeg * 16]     = b0;
            *(uint4*)&Bs_hi[ldRow * GS_STRIDE + ldSeg * 16 + 8] = b1;
            *(uint4*)&Bs_lo[ldRow * GS_STRIDE + ldSeg * 16]     = b2;
            *(uint4*)&Bs_lo[ldRow * GS_STRIDE + ldSeg * 16 + 8] = b3;
        }
        __syncthreads();

        #pragma unroll
        for (int kt = 0; kt < 4; kt++) {
            const int k0 = kt * 16 + tig * 2;
            uint32_t Ah[2][4], Al[2][4], Bh[4][2], Bl[4][2];
            #pragma unroll
            for (int mt = 0; mt < 2; mt++) {
                int m = wm * 32 + mt * 16 + grp;
                Ah[mt][0] = *(const uint32_t*)&As_hi[(m    ) * GS_STRIDE + k0];
                Ah[mt][1] = *(const uint32_t*)&As_hi[(m + 8) * GS_STRIDE + k0];
                Ah[mt][2] = *(const uint32_t*)&As_hi[(m    ) * GS_STRIDE + k0 + 8];
                Ah[mt][3] = *(const uint32_t*)&As_hi[(m + 8) * GS_STRIDE + k0 + 8];
                Al[mt][0] = *(const uint32_t*)&As_lo[(m    ) * GS_STRIDE + k0];
                Al[mt][1] = *(const uint32_t*)&As_lo[(m + 8) * GS_STRIDE + k0];
                Al[mt][2] = *(const uint32_t*)&As_lo[(m    ) * GS_STRIDE + k0 + 8];
                Al[mt][3] = *(const uint32_t*)&As_lo[(m + 8) * GS_STRIDE + k0 + 8];
            }
            #pragma unroll
            for (int nt = 0; nt < 4; nt++) {
                int n = wn * 32 + nt * 8 + grp;
                Bh[nt][0] = *(const uint32_t*)&Bs_hi[n * GS_STRIDE + k0];
                Bh[nt][1] = *(const uint32_t*)&Bs_hi[n * GS_STRIDE + k0 + 8];
                Bl[nt][0] = *(const uint32_t*)&Bs_lo[n * GS_STRIDE + k0];
                Bl[nt][1] = *(const uint32_t*)&Bs_lo[n * GS_STRIDE + k0 + 8];
            }
            #pragma unroll
            for (int mt = 0; mt < 2; mt++)
                #pragma unroll
                for (int nt = 0; nt < 4; nt++) {
                    mma_bf16(acc[mt][nt], Ah[mt], Bh[nt]);
                    mma_bf16(acc[mt][nt], Al[mt], Bh[nt]);
                    mma_bf16(acc[mt][nt], Ah[mt], Bl[nt]);
                }
        }
        __syncthreads();
    }

    // epilogue: + bias[m], store float2 along b
    #pragma unroll
    for (int mt = 0; mt < 2; mt++)
        #pragma unroll
        for (int rr = 0; rr < 2; rr++) {
            int m_local = wm * 32 + mt * 16 + grp + rr * 8;
            float bv = g_bias[mtile * 128 + m_local];
            size_t rowbase = ((size_t)t * NCOLS + mtile * 128 + m_local) * BATCH;
            #pragma unroll
            for (int nt = 0; nt < 4; nt++) {
                int b = wn * 32 + nt * 8 + tig * 2;
                *(float2*)(g_xg + rowbase + b) =
                    make_float2(acc[mt][nt][rr * 2] + bv, acc[mt][nt][rr * 2 + 1] + bv);
            }
        }

    __threadfence();
    __syncthreads();
    if (tid == 0) atomicAdd(&g_xg_ready[t], 1);
}

// ---------------------------------------------------------------------------
// Persistent HMMA recurrence (R11-proven shape).
// grid = 64 CTAs: dir = blk>>5, q = blk&31 owns j in [q*8, q*8+8).
// 128 threads = 4 warps; warp w owns batches [w*32, w*32+32).
// Per-CTA GEMM: M=128 (batch), N=32 (4 gates x 8 j), K=256, bf16x3.
// xg loads hoisted before the sibling barrier.
// ---------------------------------------------------------------------------
#define HS_STRIDE 264
#define HS_ELEMS  (128 * HS_STRIDE)
#define WS_ELEMS  (32 * HS_STRIDE)
#define SMEM_TOTAL ((2 * HS_ELEMS + 2 * WS_ELEMS) * 2)

extern "C" __global__ void __launch_bounds__(128) lstm_mma_kernel(
    const float* __restrict__ Whh_f, const float* __restrict__ Whh_b,
    const float* __restrict__ c0, float* __restrict__ out)
{
    extern __shared__ __nv_bfloat16 smem[];
    __nv_bfloat16* hs_hi = smem;
    __nv_bfloat16* hs_lo = smem + HS_ELEMS;
    __nv_bfloat16* ws_hi = smem + 2 * HS_ELEMS;
    __nv_bfloat16* ws_lo = smem + 2 * HS_ELEMS + WS_ELEMS;

    const int blk = blockIdx.x;
    const int dir = blk >> 5;
    const int q   = blk & 31;
    const int tid = threadIdx.x;
    const int w   = tid >> 5;
    const int ln  = tid & 31;
    const int grp = ln >> 2;
    const int tig = ln & 3;

    const float* Whh = dir ? Whh_b : Whh_f;

    for (int i = tid; i < 32 * HID; i += 128) {
        int n = i >> 8, k = i & 255;
        int wrow = (n >> 3) * HID + q * 8 + (n & 7);
        float wv = Whh[(size_t)wrow * HID + k];
        __nv_bfloat16 wh = __float2bfloat16(wv);
        ws_hi[n * HS_STRIDE + k] = wh;
        ws_lo[n * HS_STRIDE + k] = __float2bfloat16(wv - __bfloat162float(wh));
    }

    float cr[8];
    #pragma unroll
    for (int mt = 0; mt < 2; mt++)
        #pragma unroll
        for (int rr = 0; rr < 2; rr++)
            #pragma unroll
            for (int jb = 0; jb < 2; jb++) {
                int b = w * 32 + mt * 16 + grp + rr * 8;
                int j = q * 8 + tig * 2 + jb;
                cr[mt * 4 + rr * 2 + jb] =
                    c0[(size_t)dir * BATCH * HID + (size_t)b * HID + j];
            }

    __syncthreads();

    for (int s = 0; s < T_STEPS; s++) {
        const int t = dir ? (T_STEPS - 1 - s) : s;

        // ---- wait: xg[t] produced ----
        if (tid == 0) {
            volatile int* px = &g_xg_ready[t];
            while (*px < GEMM_BLKS_PER_T) __nanosleep(64);
        }
        __syncthreads();

        // ---- prefetch xg into accumulators (overlaps the sibling barrier) ----
        float acc[2][4][4];
        #pragma unroll
        for (int mt = 0; mt < 2; mt++)
            #pragma unroll
            for (int nt = 0; nt < 4; nt++)
                #pragma unroll
                for (int rr = 0; rr < 2; rr++)
                    #pragma unroll
                    for (int jb = 0; jb < 2; jb++) {
                        int b = w * 32 + mt * 16 + grp + rr * 8;
                        int ncol = dir * 1024 + nt * 256 + q * 8 + tig * 2 + jb;
                        acc[mt][nt][rr * 2 + jb] =
                            __ldcg(g_xg + ((size_t)t * NCOLS + ncol) * BATCH + b);
                    }

        // ---- wait: all CTAs of this dir finished step s-1 ----
        if (s > 0) {
            if (tid == 0) {
                volatile int* p = &g_bar[dir][s - 1];
                while (*p < CTAS_PER_DIR) __nanosleep(32);
            }
        }
        __syncthreads();

        // ---- stage h planes [128 x 256] bf16 into padded SMEM ----
        {
            const uint4* src_hi = (const uint4*)&g_hbf[dir][(s + 1) & 1][0][0][0];
            const uint4* src_lo = (const uint4*)&g_hbf[dir][(s + 1) & 1][1][0][0];
            #pragma unroll
            for (int i = tid; i < 4096; i += 128) {     // uint4 = 8 bf16
                int b = i >> 5, kq = i & 31;
                uint4 vh = __ldcv(src_hi + i);
                uint4 vl = __ldcv(src_lo + i);
                *(uint4*)&hs_hi[b * HS_STRIDE + kq * 8] = vh;
                *(uint4*)&hs_lo[b * HS_STRIDE + kq * 8] = vl;
            }
        }
        __syncthreads();

        // ---- K loop: 16 k-tiles x (2 mt x 4 nt) x 3 passes ----
        #pragma unroll 4
        for (int kt = 0; kt < 16; kt++) {
            const int k0 = kt * 16 + tig * 2;
            uint32_t Ah[2][4], Al[2][4], Bh[4][2], Bl[4][2];
            #pragma unroll
            for (int mt = 0; mt < 2; mt++) {
                int b = w * 32 + mt * 16 + grp;
                Ah[mt][0] = *(const uint32_t*)&hs_hi[(b    ) * HS_STRIDE + k0];
                Ah[mt][1] = *(const uint32_t*)&hs_hi[(b + 8) * HS_STRIDE + k0];
                Ah[mt][2] = *(const uint32_t*)&hs_hi[(b    ) * HS_STRIDE + k0 + 8];
                Ah[mt][3] = *(const uint32_t*)&hs_hi[(b + 8) * HS_STRIDE + k0 + 8];
                Al[mt][0] = *(const uint32_t*)&hs_lo[(b    ) * HS_STRIDE + k0];
                Al[mt][1] = *(const uint32_t*)&hs_lo[(b + 8) * HS_STRIDE + k0];
                Al[mt][2] = *(const uint32_t*)&hs_lo[(b    ) * HS_STRIDE + k0 + 8];
                Al[mt][3] = *(const uint32_t*)&hs_lo[(b + 8) * HS_STRIDE + k0 + 8];
            }
            #pragma unroll
            for (int nt = 0; nt < 4; nt++) {
                int n = nt * 8 + grp;
                Bh[nt][0] = *(const uint32_t*)&ws_hi[n * HS_STRIDE + k0];
                Bh[nt][1] = *(const uint32_t*)&ws_hi[n * HS_STRIDE + k0 + 8];
                Bl[nt][0] = *(const uint32_t*)&ws_lo[n * HS_STRIDE + k0];
                Bl[nt][1] = *(const uint32_t*)&ws_lo[n * HS_STRIDE + k0 + 8];
            }
            #pragma unroll
            for (int mt = 0; mt < 2; mt++)
                #pragma unroll
                for (int nt = 0; nt < 4; nt++) {
                    mma_bf16(acc[mt][nt], Ah[mt], Bh[nt]);
                    mma_bf16(acc[mt][nt], Al[mt], Bh[nt]);
                    mma_bf16(acc[mt][nt], Ah[mt], Bl[nt]);
                }
        }

        // ---- epilogue: gates, c/h update, publish ----
        __nv_bfloat16* hb_hi = &g_hbf[dir][s & 1][0][0][0];
        __nv_bfloat16* hb_lo = &g_hbf[dir][s & 1][1][0][0];
        #pragma unroll
        for (int mt = 0; mt < 2; mt++)
            #pragma unroll
            for (int rr = 0; rr < 2; rr++)
                #pragma unroll
                for (int jb = 0; jb < 2; jb++) {
                    int b = w * 32 + mt * 16 + grp + rr * 8;
                    int j = q * 8 + tig * 2 + jb;
                    int ci = mt * 4 + rr * 2 + jb;
                    int di = rr * 2 + jb;
                    float Gi = acc[mt][0][di];
                    float Gf = acc[mt][1][di];
                    float Gg = acc[mt][2][di];
                    float Go = acc[mt][3][di];
                    float cn = sigm(Gf) * cr[ci] + sigm(Gi) * tanhf(Gg);
                    float hn = sigm(Go) * tanhf(cn);
                    cr[ci] = cn;
                    out[(size_t)t * BATCH * OUT_TB_STRIDE + (size_t)b * OUT_TB_STRIDE
                        + dir * HID + j] = hn;
                    __nv_bfloat16 hh = __float2bfloat16(hn);
                    hb_hi[(size_t)b * HID + j] = hh;
                    hb_lo[(size_t)b * HID + j] = __float2bfloat16(hn - __bfloat162float(hh));
                    if (s == T_STEPS - 1) {
                        float* tail_h = out + OUT_MAIN + dir * 65536;
                        float* tail_c = tail_h + 32768;
                        tail_h[b * HID + j] = hn;
                        tail_c[b * HID + j] = cn;
                    }
                }

        // ---- release ----
        __threadfence();
        __syncthreads();
        if (tid == 0) atomicAdd(&g_bar[dir][s], 1);
    }
}

// ---------------------------------------------------------------------------
extern "C" void kernel_launch(void* const* d_in, const int* in_sizes, int n_in,
                              void* d_out, int out_size)
{
    const float* x     = (const float*)d_in[0];
    const float* h0    = (const float*)d_in[1];
    const float* c0    = (const float*)d_in[2];
    const float* Wih_f = (const float*)d_in[3];
    const float* Whh_f = (const float*)d_in[4];
    const float* bih_f = (const float*)d_in[5];
    const float* bhh_f = (const float*)d_in[6];
    const float* Wih_b = (const float*)d_in[7];
    const float* Whh_b = (const float*)d_in[8];
    const float* bih_b = (const float*)d_in[9];
    const float* bhh_b = (const float*)d_in[10];
    float* out = (float*)d_out;

    static cudaStream_t s_gemm = nullptr;
    static cudaEvent_t ev_fork = nullptr, ev_join = nullptr;
    if (!s_gemm) {
        cudaStreamCreateWithFlags(&s_gemm, cudaStreamNonBlocking);
        cudaEventCreateWithFlags(&ev_fork, cudaEventDisableTiming);
        cudaEventCreateWithFlags(&ev_join, cudaEventDisableTiming);
    }

    cudaFuncSetAttribute(lstm_mma_kernel,
                         cudaFuncAttributeMaxDynamicSharedMemorySize, SMEM_TOTAL);
    cudaFuncSetAttribute(gemm_hmma_kernel,
                         cudaFuncAttributeMaxDynamicSharedMemorySize, GEMM_SMEM);

    // init + splits on the capture stream
    init_misc_kernel<<<256, 256>>>(h0);
    split_w_kernel<<<2048, 256>>>(Wih_f, Wih_b, bih_f, bhh_f, bih_b, bhh_b);
    split_x_kernel<<<8192, 256>>>(x);

    // fork: side stream runs the HMMA xg gemm concurrently
    cudaEventRecord(ev_fork, 0);
    cudaStreamWaitEvent(s_gemm, ev_fork, 0);
    gemm_hmma_kernel<<<dim3(16, 512), 512, GEMM_SMEM, s_gemm>>>();
    cudaEventRecord(ev_join, s_gemm);

    // main stream: persistent HMMA recurrence (consumes xg per-t)
    lstm_mma_kernel<<<2 * CTAS_PER_DIR, 128, SMEM_TOTAL>>>(Whh_f, Whh_b, c0, out);

    // join
    cudaStreamWaitEvent(0, ev_join, 0);
}